// round 14
// baseline (speedup 1.0000x reference)
#include <cuda_runtime.h>
#include <cstdint>

// CMFMLoss: B=64, T=1024, D=256. Single fused kernel, cp.async smem pipeline.
// Identity: sum_{i!=j} cross_cos[i,j]
//   = (1/T) * [ sum_t <sum_i vn[i,t,:], sum_j an[j,t,:]>  -  sum_{b,t} cos_bt ]
// 16 stages x 4 rows; depth-2 cp.async double buffer (8KB/stage). Lookahead
// lives in SMEM, not registers -> low regs + deep MLP simultaneously.

#define Bb 64
#define Tt 1024
#define Dd 256
#define NBLK 1024
#define EPS2 1e-16f
#define NSTAGE 16
#define RPS 4            // rows per stage

__device__ float    g_cr[NBLK];
__device__ float    g_cp[NBLK];
__device__ float    g_ca[NBLK];
__device__ unsigned g_done = 0;

__device__ __forceinline__ float dot8(const float4& x0, const float4& x1,
                                      const float4& y0, const float4& y1) {
    float s = x0.x * y0.x;
    s = fmaf(x0.y, y0.y, s); s = fmaf(x0.z, y0.z, s); s = fmaf(x0.w, y0.w, s);
    s = fmaf(x1.x, y1.x, s); s = fmaf(x1.y, y1.y, s);
    s = fmaf(x1.z, y1.z, s); s = fmaf(x1.w, y1.w, s);
    return s;
}

__device__ __forceinline__ float bfly_add(float v) {
    #pragma unroll
    for (int off = 16; off > 0; off >>= 1)
        v += __shfl_xor_sync(0xffffffffu, v, off);
    return v;
}

__device__ __forceinline__ void cp16(uint32_t dst, const float* src) {
    asm volatile("cp.async.cg.shared.global [%0], [%1], 16;" :: "r"(dst), "l"(src));
}

// Issue one stage (4 rows of v + 4 rows of a, 8KB) into buffer `buf`.
// Thread covers: rows {r0, r0+2} of each tensor, 16B chunk `off`.
__device__ __forceinline__ void issue_stage(const float* __restrict__ fv,
                                            const float* __restrict__ fa,
                                            int t, int s, int buf,
                                            uint32_t pool_sh, int r0, int off)
{
    #pragma unroll
    for (int k = 0; k < 2; ++k) {
        const int row = r0 + 2 * k;
        const int b   = s * RPS + row;
        const size_t g = ((size_t)b * Tt + t) * Dd + (size_t)off * 4;
        const uint32_t dv = pool_sh + (uint32_t)(buf * 8192 + row * 1024 + off * 16);
        cp16(dv,        fv + g);
        cp16(dv + 4096, fa + g);
    }
    asm volatile("cp.async.commit_group;");
}

__global__ void __launch_bounds__(128, 8)
cmfm_fused(const float* __restrict__ fv,
           const float* __restrict__ fa,
           const long long* __restrict__ labels,
           float* __restrict__ out)
{
    const int t    = blockIdx.x;
    const int tid  = threadIdx.x;
    const int lane = tid & 31;
    const int w    = tid >> 5;   // warp 0..3

    __shared__ float4 pool[1024];     // 16KB: 2 bufs x (4 v-rows + 4 a-rows) x 64 f4
    __shared__ float  s_wb[Bb];
    __shared__ float  s_cp[4], s_ca[4], s_red[4];
    __shared__ int    s_last;

    const uint32_t pool_sh = (uint32_t)__cvta_generic_to_shared(pool);

    if (tid < Bb) s_wb[tid] = (labels[tid] == 0) ? 1.0f : 0.0f;

    const int r0  = tid >> 6;    // 0 or 1
    const int off = tid & 63;    // float4 chunk within the 1KB row

    // Prologue: stages 0 and 1 in flight.
    issue_stage(fv, fa, t, 0, 0, pool_sh, r0, off);
    issue_stage(fv, fa, t, 1, 1, pool_sh, r0, off);

    float sv0=0.f,sv1=0.f,sv2=0.f,sv3=0.f,sv4=0.f,sv5=0.f,sv6=0.f,sv7=0.f;
    float sa0=0.f,sa1=0.f,sa2=0.f,sa3=0.f,sa4=0.f,sa5=0.f,sa6=0.f,sa7=0.f;
    float c_all = 0.f, c_pos = 0.f;

    for (int s = 0; s < NSTAGE; ++s) {
        const int buf = s & 1;
        if (s == NSTAGE - 1) { asm volatile("cp.async.wait_group 0;"); }
        else                 { asm volatile("cp.async.wait_group 1;"); }
        __syncthreads();

        // Warp w consumes row w of this stage (b = s*4 + w).
        const float4* vrow = pool + (size_t)buf * 512 + (size_t)w * 64;
        const float4* arow = vrow + 256;
        const float4 v0 = vrow[lane], v1 = vrow[lane + 32];
        const float4 a0 = arow[lane], a1 = arow[lane + 32];

        float nv = dot8(v0, v1, v0, v1);
        float na = dot8(a0, a1, a0, a1);
        const float dtp = dot8(v0, v1, a0, a1);   // per-lane partial

        #pragma unroll
        for (int o = 16; o > 0; o >>= 1) {
            nv += __shfl_xor_sync(0xffffffffu, nv, o);
            na += __shfl_xor_sync(0xffffffffu, na, o);
        }

        const float invV = rsqrtf(fmaxf(nv, EPS2));
        const float invA = rsqrtf(fmaxf(na, EPS2));

        sv0 = fmaf(v0.x, invV, sv0); sv1 = fmaf(v0.y, invV, sv1);
        sv2 = fmaf(v0.z, invV, sv2); sv3 = fmaf(v0.w, invV, sv3);
        sv4 = fmaf(v1.x, invV, sv4); sv5 = fmaf(v1.y, invV, sv5);
        sv6 = fmaf(v1.z, invV, sv6); sv7 = fmaf(v1.w, invV, sv7);
        sa0 = fmaf(a0.x, invA, sa0); sa1 = fmaf(a0.y, invA, sa1);
        sa2 = fmaf(a0.z, invA, sa2); sa3 = fmaf(a0.w, invA, sa3);
        sa4 = fmaf(a1.x, invA, sa4); sa5 = fmaf(a1.y, invA, sa5);
        sa6 = fmaf(a1.z, invA, sa6); sa7 = fmaf(a1.w, invA, sa7);

        const float wb = s_wb[s * RPS + w];
        const float c  = dtp * (invV * invA);
        c_all += c;
        c_pos = fmaf(c, wb, c_pos);

        __syncthreads();   // everyone done reading buf before refill
        if (s + 2 < NSTAGE)
            issue_stage(fv, fa, t, s + 2, buf, pool_sh, r0, off);
    }

    // Warp totals for the cosine sums.
    c_all = bfly_add(c_all);
    c_pos = bfly_add(c_pos);
    if (lane == 0) { s_cp[w] = c_pos; s_ca[w] = c_all; }

    // Overlay epilogue arrays on the (now dead) pipeline buffers.
    float* s_sv = (float*)pool;          // 4 warps x 256
    float* s_sa = (float*)pool + 1024;   // 4 warps x 256
    {
        float4* svp = reinterpret_cast<float4*>(s_sv) + (size_t)w * 64;
        float4* sap = reinterpret_cast<float4*>(s_sa) + (size_t)w * 64;
        svp[lane]      = make_float4(sv0, sv1, sv2, sv3);
        svp[lane + 32] = make_float4(sv4, sv5, sv6, sv7);
        sap[lane]      = make_float4(sa0, sa1, sa2, sa3);
        sap[lane + 32] = make_float4(sa4, sa5, sa6, sa7);
    }
    __syncthreads();

    // <Sv_t, Sa_t>: each thread covers 2 d-columns.
    const int d0 = tid;
    const int d1 = tid + 128;
    float tv0 = 0.f, ta0 = 0.f, tv1 = 0.f, ta1 = 0.f;
    #pragma unroll
    for (int ww = 0; ww < 4; ++ww) {
        tv0 += s_sv[ww * 256 + d0]; ta0 += s_sa[ww * 256 + d0];
        tv1 += s_sv[ww * 256 + d1]; ta1 += s_sa[ww * 256 + d1];
    }
    const float prod = bfly_add(fmaf(tv1, ta1, tv0 * ta0));
    if (lane == 0) s_red[w] = prod;
    __syncthreads();

    // Publish block partials; last block performs the final reduce.
    if (tid == 0) {
        float cr = 0.f, cpt = 0.f, cat = 0.f;
        #pragma unroll
        for (int ww = 0; ww < 4; ++ww) {
            cr += s_red[ww]; cpt += s_cp[ww]; cat += s_ca[ww];
        }
        g_cr[t] = cr;
        g_cp[t] = cpt;
        g_ca[t] = cat;
        __threadfence();
        const unsigned old = atomicAdd(&g_done, 1u);
        s_last = (old == NBLK - 1) ? 1 : 0;
    }
    __syncthreads();
    if (!s_last) return;

    // ---- Final reduction (one block, deterministic order) ----
    {
        float cr = 0.f, cpr = 0.f, car = 0.f;
        #pragma unroll
        for (int k = 0; k < NBLK / 128; ++k) {
            const int i = tid + k * 128;
            cr += g_cr[i]; cpr += g_cp[i]; car += g_ca[i];
        }
        cr  = bfly_add(cr);
        cpr = bfly_add(cpr);
        car = bfly_add(car);
        if (lane == 0) { s_red[w] = cr; s_cp[w] = cpr; s_ca[w] = car; }
        __syncthreads();

        if (tid == 0) {
            float Cr = 0.f, Sp = 0.f, Sa = 0.f;
            #pragma unroll
            for (int ww = 0; ww < 4; ++ww) { Cr += s_red[ww]; Sp += s_cp[ww]; Sa += s_ca[ww]; }
            const float Sn = Sa - Sp;

            int npos = 0;
            for (int b = 0; b < Bb; ++b) npos += (labels[b] == 0) ? 1 : 0;
            const float fpos = (float)npos;
            const float fneg = (float)(Bb - npos);

            const float loss_pos = 2.0f * (fpos * (float)Tt - Sp);
            const float loss_neg = 2.0f * Sn + (Cr - Sa) / (float)Tt;

            const float cnt_pos = fpos * (float)Tt;
            const float cnt_neg = fneg * (float)Tt + (float)(Bb * (Bb - 1));

            float loss = 0.f;
            if (cnt_pos > 0.f) loss += loss_pos / fmaxf(cnt_pos, 1.0f);
            if (cnt_neg > 0.f) loss += loss_neg / fmaxf(cnt_neg, 1.0f);
            out[0] = loss;

            g_done = 0;   // self-reset for next (graph-replayed) call
        }
    }
}

extern "C" void kernel_launch(void* const* d_in, const int* in_sizes, int n_in,
                              void* d_out, int out_size)
{
    const float*     fv     = (const float*)d_in[0];
    const float*     fa     = (const float*)d_in[1];
    const long long* labels = (const long long*)d_in[2];
    float*           out    = (float*)d_out;

    (void)in_sizes; (void)n_in; (void)out_size;

    cmfm_fused<<<NBLK, 128>>>(fv, fa, labels, out);
}

// round 15
// speedup vs baseline: 1.0637x; 1.0637x over previous
#include <cuda_runtime.h>
#include <cstdint>

// CMFMLoss: B=64, T=1024, D=256. Single fused kernel, cp.async smem pipeline.
// Identity: sum_{i!=j} cross_cos[i,j]
//   = (1/T) * [ sum_t <sum_i vn[i,t,:], sum_j an[j,t,:]>  -  sum_{b,t} cos_bt ]
// 16 stages x 4 rows; THREE-buffer cp.async pipeline (24KB), one barrier per
// stage. Lookahead lives in SMEM: 8 CTAs/SM x up to 2 stages in flight.

#define Bb 64
#define Tt 1024
#define Dd 256
#define NBLK 1024
#define EPS2 1e-16f
#define NSTAGE 16
#define RPS 4            // rows per stage

__device__ float    g_cr[NBLK];
__device__ float    g_cp[NBLK];
__device__ float    g_ca[NBLK];
__device__ unsigned g_done = 0;

__device__ __forceinline__ float dot8(const float4& x0, const float4& x1,
                                      const float4& y0, const float4& y1) {
    float s = x0.x * y0.x;
    s = fmaf(x0.y, y0.y, s); s = fmaf(x0.z, y0.z, s); s = fmaf(x0.w, y0.w, s);
    s = fmaf(x1.x, y1.x, s); s = fmaf(x1.y, y1.y, s);
    s = fmaf(x1.z, y1.z, s); s = fmaf(x1.w, y1.w, s);
    return s;
}

__device__ __forceinline__ float bfly_add(float v) {
    #pragma unroll
    for (int off = 16; off > 0; off >>= 1)
        v += __shfl_xor_sync(0xffffffffu, v, off);
    return v;
}

__device__ __forceinline__ void cp16(uint32_t dst, const float* src) {
    asm volatile("cp.async.cg.shared.global [%0], [%1], 16;" :: "r"(dst), "l"(src));
}

// Issue one stage (4 rows of v + 4 rows of a, 8KB) into buffer `buf`.
// Thread covers rows {r0, r0+2} of each tensor, 16B chunk `off`.
__device__ __forceinline__ void issue_stage(const float* __restrict__ fv,
                                            const float* __restrict__ fa,
                                            int t, int s, int buf,
                                            uint32_t pool_sh, int r0, int off)
{
    #pragma unroll
    for (int k = 0; k < 2; ++k) {
        const int row = r0 + 2 * k;
        const int b   = s * RPS + row;
        const size_t g = ((size_t)b * Tt + t) * Dd + (size_t)off * 4;
        const uint32_t dv = pool_sh + (uint32_t)(buf * 8192 + row * 1024 + off * 16);
        cp16(dv,        fv + g);
        cp16(dv + 4096, fa + g);
    }
    asm volatile("cp.async.commit_group;");
}

__global__ void __launch_bounds__(128, 8)
cmfm_fused(const float* __restrict__ fv,
           const float* __restrict__ fa,
           const long long* __restrict__ labels,
           float* __restrict__ out)
{
    const int t    = blockIdx.x;
    const int tid  = threadIdx.x;
    const int lane = tid & 31;
    const int w    = tid >> 5;   // warp 0..3

    __shared__ float4 pool[1536];     // 24KB: 3 bufs x (4 v-rows + 4 a-rows)
    __shared__ float  s_wb[Bb];
    __shared__ float  s_cp[4], s_ca[4], s_red[4];
    __shared__ int    s_last;

    const uint32_t pool_sh = (uint32_t)__cvta_generic_to_shared(pool);

    if (tid < Bb) s_wb[tid] = (labels[tid] == 0) ? 1.0f : 0.0f;

    const int r0  = tid >> 6;    // 0 or 1
    const int off = tid & 63;    // float4 chunk within the 1KB row

    // Prologue: stages 0 and 1 in flight.
    issue_stage(fv, fa, t, 0, 0, pool_sh, r0, off);
    issue_stage(fv, fa, t, 1, 1, pool_sh, r0, off);

    float sv0=0.f,sv1=0.f,sv2=0.f,sv3=0.f,sv4=0.f,sv5=0.f,sv6=0.f,sv7=0.f;
    float sa0=0.f,sa1=0.f,sa2=0.f,sa3=0.f,sa4=0.f,sa5=0.f,sa6=0.f,sa7=0.f;
    float c_all = 0.f, c_pos = 0.f;

    #pragma unroll
    for (int s = 0; s < NSTAGE; ++s) {
        const int buf = s % 3;
        if (s < NSTAGE - 1) { asm volatile("cp.async.wait_group 1;"); }
        else                { asm volatile("cp.async.wait_group 0;"); }
        __syncthreads();    // stage s visible to all; stage s-1 reads all done

        // Refill: stage s+2 goes into buf (s+2)%3 == (s-1)%3, whose readers
        // finished before the barrier above. Issue BEFORE consuming so the
        // loads overlap this stage's compute.
        if (s + 2 < NSTAGE)
            issue_stage(fv, fa, t, s + 2, (s + 2) % 3, pool_sh, r0, off);

        // Warp w consumes row w of this stage (b = s*4 + w).
        const float4* vrow = pool + (size_t)buf * 512 + (size_t)w * 64;
        const float4* arow = vrow + 256;
        const float4 v0 = vrow[lane], v1 = vrow[lane + 32];
        const float4 a0 = arow[lane], a1 = arow[lane + 32];

        float nv = dot8(v0, v1, v0, v1);
        float na = dot8(a0, a1, a0, a1);
        const float dtp = dot8(v0, v1, a0, a1);   // per-lane partial

        #pragma unroll
        for (int o = 16; o > 0; o >>= 1) {
            nv += __shfl_xor_sync(0xffffffffu, nv, o);
            na += __shfl_xor_sync(0xffffffffu, na, o);
        }

        const float invV = rsqrtf(fmaxf(nv, EPS2));
        const float invA = rsqrtf(fmaxf(na, EPS2));

        sv0 = fmaf(v0.x, invV, sv0); sv1 = fmaf(v0.y, invV, sv1);
        sv2 = fmaf(v0.z, invV, sv2); sv3 = fmaf(v0.w, invV, sv3);
        sv4 = fmaf(v1.x, invV, sv4); sv5 = fmaf(v1.y, invV, sv5);
        sv6 = fmaf(v1.z, invV, sv6); sv7 = fmaf(v1.w, invV, sv7);
        sa0 = fmaf(a0.x, invA, sa0); sa1 = fmaf(a0.y, invA, sa1);
        sa2 = fmaf(a0.z, invA, sa2); sa3 = fmaf(a0.w, invA, sa3);
        sa4 = fmaf(a1.x, invA, sa4); sa5 = fmaf(a1.y, invA, sa5);
        sa6 = fmaf(a1.z, invA, sa6); sa7 = fmaf(a1.w, invA, sa7);

        const float wb = s_wb[s * RPS + w];
        const float c  = dtp * (invV * invA);
        c_all += c;
        c_pos = fmaf(c, wb, c_pos);
    }

    // Warp totals for the cosine sums.
    c_all = bfly_add(c_all);
    c_pos = bfly_add(c_pos);
    if (lane == 0) { s_cp[w] = c_pos; s_ca[w] = c_all; }

    __syncthreads();   // pipeline fully drained; pool is dead, reuse it

    // Overlay epilogue arrays on the pipeline buffers.
    float* s_sv = (float*)pool;          // 4 warps x 256
    float* s_sa = (float*)pool + 1024;   // 4 warps x 256
    {
        float4* svp = reinterpret_cast<float4*>(s_sv) + (size_t)w * 64;
        float4* sap = reinterpret_cast<float4*>(s_sa) + (size_t)w * 64;
        svp[lane]      = make_float4(sv0, sv1, sv2, sv3);
        svp[lane + 32] = make_float4(sv4, sv5, sv6, sv7);
        sap[lane]      = make_float4(sa0, sa1, sa2, sa3);
        sap[lane + 32] = make_float4(sa4, sa5, sa6, sa7);
    }
    __syncthreads();

    // <Sv_t, Sa_t>: each thread covers 2 d-columns.
    const int d0 = tid;
    const int d1 = tid + 128;
    float tv0 = 0.f, ta0 = 0.f, tv1 = 0.f, ta1 = 0.f;
    #pragma unroll
    for (int ww = 0; ww < 4; ++ww) {
        tv0 += s_sv[ww * 256 + d0]; ta0 += s_sa[ww * 256 + d0];
        tv1 += s_sv[ww * 256 + d1]; ta1 += s_sa[ww * 256 + d1];
    }
    const float prod = bfly_add(fmaf(tv1, ta1, tv0 * ta0));
    if (lane == 0) s_red[w] = prod;
    __syncthreads();

    // Publish block partials; last block performs the final reduce.
    if (tid == 0) {
        float cr = 0.f, cpt = 0.f, cat = 0.f;
        #pragma unroll
        for (int ww = 0; ww < 4; ++ww) {
            cr += s_red[ww]; cpt += s_cp[ww]; cat += s_ca[ww];
        }
        g_cr[t] = cr;
        g_cp[t] = cpt;
        g_ca[t] = cat;
        __threadfence();
        const unsigned old = atomicAdd(&g_done, 1u);
        s_last = (old == NBLK - 1) ? 1 : 0;
    }
    __syncthreads();
    if (!s_last) return;

    // ---- Final reduction (one block, deterministic order) ----
    {
        float cr = 0.f, cpr = 0.f, car = 0.f;
        #pragma unroll
        for (int k = 0; k < NBLK / 128; ++k) {
            const int i = tid + k * 128;
            cr += g_cr[i]; cpr += g_cp[i]; car += g_ca[i];
        }
        cr  = bfly_add(cr);
        cpr = bfly_add(cpr);
        car = bfly_add(car);
        if (lane == 0) { s_red[w] = cr; s_cp[w] = cpr; s_ca[w] = car; }
        __syncthreads();

        if (tid == 0) {
            float Cr = 0.f, Sp = 0.f, Sa = 0.f;
            #pragma unroll
            for (int ww = 0; ww < 4; ++ww) { Cr += s_red[ww]; Sp += s_cp[ww]; Sa += s_ca[ww]; }
            const float Sn = Sa - Sp;

            int npos = 0;
            for (int b = 0; b < Bb; ++b) npos += (labels[b] == 0) ? 1 : 0;
            const float fpos = (float)npos;
            const float fneg = (float)(Bb - npos);

            const float loss_pos = 2.0f * (fpos * (float)Tt - Sp);
            const float loss_neg = 2.0f * Sn + (Cr - Sa) / (float)Tt;

            const float cnt_pos = fpos * (float)Tt;
            const float cnt_neg = fneg * (float)Tt + (float)(Bb * (Bb - 1));

            float loss = 0.f;
            if (cnt_pos > 0.f) loss += loss_pos / fmaxf(cnt_pos, 1.0f);
            if (cnt_neg > 0.f) loss += loss_neg / fmaxf(cnt_neg, 1.0f);
            out[0] = loss;

            g_done = 0;   // self-reset for next (graph-replayed) call
        }
    }
}

extern "C" void kernel_launch(void* const* d_in, const int* in_sizes, int n_in,
                              void* d_out, int out_size)
{
    const float*     fv     = (const float*)d_in[0];
    const float*     fa     = (const float*)d_in[1];
    const long long* labels = (const long long*)d_in[2];
    float*           out    = (float*)d_out;

    (void)in_sizes; (void)n_in; (void)out_size;

    cmfm_fused<<<NBLK, 128>>>(fv, fa, labels, out);
}

// round 17
// speedup vs baseline: 1.5058x; 1.4157x over previous
#include <cuda_runtime.h>
#include <cstdint>

// CMFMLoss: B=64, T=1024, D=256. Single fused streaming kernel.
// Identity: sum_{i!=j} cross_cos[i,j]
//   = (1/T) * [ sum_t <sum_i vn[i,t,:], sum_j an[j,t,:]>  -  sum_{b,t} cos_bt ]
// R13 shape (128 thr, 4 warps x 16 rows, depth-1 register pipeline), 256-bit
// loads (sm_103 requires v8.b32 for L2 evict hints): fv pinned evict_last
// (64MB resident in ~126MB L2 across graph replays), fa streams evict_first.

#define Bb 64
#define Tt 1024
#define Dd 256
#define NBLK 1024
#define EPS2 1e-16f

__device__ float    g_cr[NBLK];
__device__ float    g_cp[NBLK];
__device__ float    g_ca[NBLK];
__device__ unsigned g_done = 0;

// 256-bit loads with L2 eviction priority (sm_103: hints require v8.b32).
__device__ __forceinline__ void ldg256_keep(const float* p, float4& lo, float4& hi) {
    uint32_t r0,r1,r2,r3,r4,r5,r6,r7;
    asm("ld.global.nc.L2::evict_last.v8.b32 {%0,%1,%2,%3,%4,%5,%6,%7}, [%8];"
        : "=r"(r0),"=r"(r1),"=r"(r2),"=r"(r3),
          "=r"(r4),"=r"(r5),"=r"(r6),"=r"(r7) : "l"(p));
    lo.x=__uint_as_float(r0); lo.y=__uint_as_float(r1);
    lo.z=__uint_as_float(r2); lo.w=__uint_as_float(r3);
    hi.x=__uint_as_float(r4); hi.y=__uint_as_float(r5);
    hi.z=__uint_as_float(r6); hi.w=__uint_as_float(r7);
}
__device__ __forceinline__ void ldg256_stream(const float* p, float4& lo, float4& hi) {
    uint32_t r0,r1,r2,r3,r4,r5,r6,r7;
    asm("ld.global.nc.L2::evict_first.v8.b32 {%0,%1,%2,%3,%4,%5,%6,%7}, [%8];"
        : "=r"(r0),"=r"(r1),"=r"(r2),"=r"(r3),
          "=r"(r4),"=r"(r5),"=r"(r6),"=r"(r7) : "l"(p));
    lo.x=__uint_as_float(r0); lo.y=__uint_as_float(r1);
    lo.z=__uint_as_float(r2); lo.w=__uint_as_float(r3);
    hi.x=__uint_as_float(r4); hi.y=__uint_as_float(r5);
    hi.z=__uint_as_float(r6); hi.w=__uint_as_float(r7);
}

__device__ __forceinline__ float dot8(const float4& x0, const float4& x1,
                                      const float4& y0, const float4& y1) {
    float s = x0.x * y0.x;
    s = fmaf(x0.y, y0.y, s); s = fmaf(x0.z, y0.z, s); s = fmaf(x0.w, y0.w, s);
    s = fmaf(x1.x, y1.x, s); s = fmaf(x1.y, y1.y, s);
    s = fmaf(x1.z, y1.z, s); s = fmaf(x1.w, y1.w, s);
    return s;
}

__device__ __forceinline__ float bfly_add(float v) {
    #pragma unroll
    for (int off = 16; off > 0; off >>= 1)
        v += __shfl_xor_sync(0xffffffffu, v, off);
    return v;
}

__global__ void __launch_bounds__(128, 7)
cmfm_fused(const float* __restrict__ fv,
           const float* __restrict__ fa,
           const long long* __restrict__ labels,
           float* __restrict__ out)
{
    const int t    = blockIdx.x;
    const int lane = threadIdx.x & 31;
    const int w    = threadIdx.x >> 5;   // warp 0..3

    __shared__ float s_sv[4][Dd];
    __shared__ float s_sa[4][Dd];
    __shared__ float s_cp[4];
    __shared__ float s_ca[4];
    __shared__ float s_red[4];
    __shared__ int   s_last;

    // One label LDG per lane; lane j holds weight of row (w*16 + (j&15)).
    const float wb_mine = (labels[w * 16 + (lane & 15)] == 0) ? 1.0f : 0.0f;

    float sv0=0.f,sv1=0.f,sv2=0.f,sv3=0.f,sv4=0.f,sv5=0.f,sv6=0.f,sv7=0.f;
    float sa0=0.f,sa1=0.f,sa2=0.f,sa3=0.f,sa4=0.f,sa5=0.f,sa6=0.f,sa7=0.f;
    float c_all = 0.f, c_pos = 0.f;     // per-lane partial cosine sums

    // Lane owns d in [8*lane, 8*lane+8): one 32B v8 load per tensor per row.
    const size_t row0  = ((size_t)(w * 16) * Tt + t) * Dd + (size_t)(lane * 8);
    const size_t rstep = (size_t)Tt * Dd;   // +1 in b

    // Prologue: load row 0 (fv pinned, fa streaming).
    float4 cv0, cv1, ca0, ca1;
    ldg256_keep  (fv + row0, cv0, cv1);
    ldg256_stream(fa + row0, ca0, ca1);

    #pragma unroll
    for (int i = 0; i < 16; ++i) {
        float4 pv0, pv1, pa0, pa1;
        if (i < 15) {
            ldg256_keep  (fv + row0 + (size_t)(i + 1) * rstep, pv0, pv1);
            ldg256_stream(fa + row0 + (size_t)(i + 1) * rstep, pa0, pa1);
        }

        float nv = dot8(cv0, cv1, cv0, cv1);
        float na = dot8(ca0, ca1, ca0, ca1);
        const float dtp = dot8(cv0, cv1, ca0, ca1);   // per-lane partial

        #pragma unroll
        for (int off = 16; off > 0; off >>= 1) {
            nv += __shfl_xor_sync(0xffffffffu, nv, off);
            na += __shfl_xor_sync(0xffffffffu, na, off);
        }

        const float invV = rsqrtf(fmaxf(nv, EPS2));
        const float invA = rsqrtf(fmaxf(na, EPS2));

        sv0 = fmaf(cv0.x, invV, sv0); sv1 = fmaf(cv0.y, invV, sv1);
        sv2 = fmaf(cv0.z, invV, sv2); sv3 = fmaf(cv0.w, invV, sv3);
        sv4 = fmaf(cv1.x, invV, sv4); sv5 = fmaf(cv1.y, invV, sv5);
        sv6 = fmaf(cv1.z, invV, sv6); sv7 = fmaf(cv1.w, invV, sv7);
        sa0 = fmaf(ca0.x, invA, sa0); sa1 = fmaf(ca0.y, invA, sa1);
        sa2 = fmaf(ca0.z, invA, sa2); sa3 = fmaf(ca0.w, invA, sa3);
        sa4 = fmaf(ca1.x, invA, sa4); sa5 = fmaf(ca1.y, invA, sa5);
        sa6 = fmaf(ca1.z, invA, sa6); sa7 = fmaf(ca1.w, invA, sa7);

        // Per-row label weight via shuffle (no memory access).
        const float wb = __shfl_sync(0xffffffffu, wb_mine, i);
        const float c  = dtp * (invV * invA);
        c_all += c;
        c_pos = fmaf(c, wb, c_pos);

        // Rotate buffers (renamed away by SSA under full unroll).
        cv0 = pv0; cv1 = pv1; ca0 = pa0; ca1 = pa1;
    }

    // Warp totals for the cosine sums.
    c_all = bfly_add(c_all);
    c_pos = bfly_add(c_pos);

    {
        // Lane owns d = 8*lane..8*lane+7 -> float4 slots 2*lane, 2*lane+1.
        float4* svp = reinterpret_cast<float4*>(s_sv[w]);
        float4* sap = reinterpret_cast<float4*>(s_sa[w]);
        svp[2 * lane]     = make_float4(sv0, sv1, sv2, sv3);
        svp[2 * lane + 1] = make_float4(sv4, sv5, sv6, sv7);
        sap[2 * lane]     = make_float4(sa0, sa1, sa2, sa3);
        sap[2 * lane + 1] = make_float4(sa4, sa5, sa6, sa7);
        if (lane == 0) { s_cp[w] = c_pos; s_ca[w] = c_all; }
    }
    __syncthreads();

    // <Sv_t, Sa_t> across the 4 warp partials; each thread covers 2 d-columns.
    const int d0 = threadIdx.x;
    const int d1 = threadIdx.x + 128;
    float tv0 = 0.f, ta0 = 0.f, tv1 = 0.f, ta1 = 0.f;
    #pragma unroll
    for (int ww = 0; ww < 4; ++ww) {
        tv0 += s_sv[ww][d0]; ta0 += s_sa[ww][d0];
        tv1 += s_sv[ww][d1]; ta1 += s_sa[ww][d1];
    }
    const float prod = bfly_add(fmaf(tv1, ta1, tv0 * ta0));
    if (lane == 0) s_red[w] = prod;
    __syncthreads();

    // Publish block partials; last block performs the final reduce.
    if (threadIdx.x == 0) {
        float cr = 0.f, cpt = 0.f, cat = 0.f;
        #pragma unroll
        for (int ww = 0; ww < 4; ++ww) {
            cr  += s_red[ww];
            cpt += s_cp[ww];
            cat += s_ca[ww];
        }
        g_cr[t] = cr;
        g_cp[t] = cpt;
        g_ca[t] = cat;
        __threadfence();
        const unsigned old = atomicAdd(&g_done, 1u);
        s_last = (old == NBLK - 1) ? 1 : 0;
    }
    __syncthreads();
    if (!s_last) return;

    // ---- Final reduction (one block, deterministic order) ----
    {
        float cr = 0.f, cpr = 0.f, car = 0.f;
        #pragma unroll
        for (int k = 0; k < NBLK / 128; ++k) {
            const int i = threadIdx.x + k * 128;
            cr += g_cr[i]; cpr += g_cp[i]; car += g_ca[i];
        }
        cr  = bfly_add(cr);
        cpr = bfly_add(cpr);
        car = bfly_add(car);
        if (lane == 0) { s_red[w] = cr; s_cp[w] = cpr; s_ca[w] = car; }
        __syncthreads();

        if (threadIdx.x == 0) {
            float Cr = 0.f, Sp = 0.f, Sa = 0.f;
            #pragma unroll
            for (int ww = 0; ww < 4; ++ww) { Cr += s_red[ww]; Sp += s_cp[ww]; Sa += s_ca[ww]; }
            const float Sn = Sa - Sp;

            int npos = 0;
            for (int b = 0; b < Bb; ++b) npos += (labels[b] == 0) ? 1 : 0;
            const float fpos = (float)npos;
            const float fneg = (float)(Bb - npos);

            const float loss_pos = 2.0f * (fpos * (float)Tt - Sp);
            const float loss_neg = 2.0f * Sn + (Cr - Sa) / (float)Tt;

            const float cnt_pos = fpos * (float)Tt;
            const float cnt_neg = fneg * (float)Tt + (float)(Bb * (Bb - 1));

            float loss = 0.f;
            if (cnt_pos > 0.f) loss += loss_pos / fmaxf(cnt_pos, 1.0f);
            if (cnt_neg > 0.f) loss += loss_neg / fmaxf(cnt_neg, 1.0f);
            out[0] = loss;

            g_done = 0;   // self-reset for next (graph-replayed) call
        }
    }
}

extern "C" void kernel_launch(void* const* d_in, const int* in_sizes, int n_in,
                              void* d_out, int out_size)
{
    const float*     fv     = (const float*)d_in[0];
    const float*     fa     = (const float*)d_in[1];
    const long long* labels = (const long long*)d_in[2];
    float*           out    = (float*)d_out;

    (void)in_sizes; (void)n_in; (void)out_size;

    cmfm_fused<<<NBLK, 128>>>(fv, fa, labels, out);
}